// round 3
// baseline (speedup 1.0000x reference)
#include <cuda_runtime.h>
#include <cuda_bf16.h>
#include <cstdint>

// Focal loss (log10 variant) mean over 28.3M elems. HBM-bound: 226.5 MB read.
// Single fused kernel, unroll x4 front-batched LDG.128 (1KB/warp in flight)
// to satisfy Little's law for the DRAM pipe. Deterministic last-block reduce.

#define NBLOCKS   1152
#define NTHREADS  256

__device__ float        g_partials[NBLOCKS];
__device__ unsigned int g_count = 0;

__device__ __forceinline__ float focal_elem(float p, int y) {
    bool  pos = (y != 0);
    float pt  = pos ? p : 1.0f - p;
    float om  = 1.0f - pt;
    // -log10(pt) = -log2(pt) * log10(2)
    float lt  = -__log2f(pt) * 0.3010299956639812f;
    float w   = pos ? 0.9f : 0.1f;
    return w * om * om * lt;
}

__device__ __forceinline__ float focal_vec(float4 p, int4 t) {
    float a = focal_elem(p.x, t.x);
    a += focal_elem(p.y, t.y);
    a += focal_elem(p.z, t.z);
    a += focal_elem(p.w, t.w);
    return a;
}

__global__ void __launch_bounds__(NTHREADS)
focal_fused_kernel(const float4* __restrict__ p4,
                   const int4*   __restrict__ t4,
                   int nvec, int ntail,
                   const float* __restrict__ p_tail,
                   const int*   __restrict__ t_tail,
                   float* __restrict__ out, float inv_n) {
    const int stride = gridDim.x * blockDim.x;
    const int base   = blockIdx.x * blockDim.x + threadIdx.x;

    float a0 = 0.0f, a1 = 0.0f, a2 = 0.0f, a3 = 0.0f;

    int i = base;
    // unrolled main loop: 8 independent 128B loads issued before any compute
    for (; i + 3 * stride < nvec; i += 4 * stride) {
        float4 p0 = __ldcs(p4 + i);
        float4 p1 = __ldcs(p4 + i + stride);
        float4 p2 = __ldcs(p4 + i + 2 * stride);
        float4 p3 = __ldcs(p4 + i + 3 * stride);
        int4   t0 = __ldcs(t4 + i);
        int4   t1 = __ldcs(t4 + i + stride);
        int4   t2 = __ldcs(t4 + i + 2 * stride);
        int4   t3 = __ldcs(t4 + i + 3 * stride);
        a0 += focal_vec(p0, t0);
        a1 += focal_vec(p1, t1);
        a2 += focal_vec(p2, t2);
        a3 += focal_vec(p3, t3);
    }
    // cleanup (empty when nvec divides evenly)
    for (; i < nvec; i += stride) {
        float4 p = __ldcs(p4 + i);
        int4   t = __ldcs(t4 + i);
        a0 += focal_vec(p, t);
    }
    float acc = (a0 + a1) + (a2 + a3);

    if (blockIdx.x == 0) {
        for (int k = threadIdx.x; k < ntail; k += blockDim.x)
            acc += focal_elem(p_tail[k], t_tail[k]);
    }

    // intra-block reduce
    #pragma unroll
    for (int off = 16; off > 0; off >>= 1)
        acc += __shfl_xor_sync(0xFFFFFFFFu, acc, off);

    __shared__ float smem[NTHREADS / 32];
    int lane = threadIdx.x & 31;
    int wid  = threadIdx.x >> 5;
    if (lane == 0) smem[wid] = acc;
    __syncthreads();

    __shared__ bool s_last;
    if (threadIdx.x == 0) {
        float v = 0.0f;
        #pragma unroll
        for (int w = 0; w < NTHREADS / 32; w++) v += smem[w];
        g_partials[blockIdx.x] = v;
        __threadfence();
        unsigned int prev = atomicAdd(&g_count, 1u);
        s_last = (prev == (unsigned int)(gridDim.x - 1));
    }
    __syncthreads();

    if (s_last) {
        // deterministic final reduction: fixed per-thread order, then tree
        float v = 0.0f;
        #pragma unroll
        for (int k = threadIdx.x; k < NBLOCKS; k += NTHREADS)
            v += g_partials[k];

        #pragma unroll
        for (int off = 16; off > 0; off >>= 1)
            v += __shfl_xor_sync(0xFFFFFFFFu, v, off);

        if (lane == 0) smem[wid] = v;
        __syncthreads();

        if (wid == 0) {
            float s = (lane < NTHREADS / 32) ? smem[lane] : 0.0f;
            #pragma unroll
            for (int off = 4; off > 0; off >>= 1)
                s += __shfl_xor_sync(0xFFFFFFFFu, s, off);
            if (lane == 0) {
                out[0] = s * inv_n;
                g_count = 0;           // reset for next graph replay
                __threadfence();
            }
        }
    }
}

extern "C" void kernel_launch(void* const* d_in, const int* in_sizes, int n_in,
                              void* d_out, int out_size) {
    const float* p = (const float*)d_in[0];
    const int*   t = (const int*)d_in[1];
    int n = in_sizes[0];

    int nvec  = n >> 2;
    int ntail = n - (nvec << 2);

    focal_fused_kernel<<<NBLOCKS, NTHREADS>>>(
        (const float4*)p, (const int4*)t, nvec, ntail,
        p + (nvec << 2), t + (nvec << 2),
        (float*)d_out, 1.0f / (float)n);
}

// round 4
// speedup vs baseline: 1.1274x; 1.1274x over previous
#include <cuda_runtime.h>
#include <cuda_bf16.h>
#include <cstdint>

// Focal loss (log10 variant) mean over 28.3M elems. HBM-bound: 226.5 MB read.
// Single fused kernel. R2 skeleton (1024 blocks x 256, single resident wave)
// + depth-2 software prefetch pipeline to double in-flight bytes per warp.
// __launch_bounds__(256, 8) pins regs <= 32 so all 1024 blocks stay resident.

#define NBLOCKS   1024
#define NTHREADS  256

__device__ float        g_partials[NBLOCKS];
__device__ unsigned int g_count = 0;

__device__ __forceinline__ float focal_elem(float p, int y) {
    bool  pos = (y != 0);
    float pt  = pos ? p : 1.0f - p;
    float om  = 1.0f - pt;
    // -log10(pt) = -log2(pt) * log10(2)
    float lt  = -__log2f(pt) * 0.3010299956639812f;
    float w   = pos ? 0.9f : 0.1f;
    return w * om * om * lt;
}

__device__ __forceinline__ float focal_vec(float4 p, int4 t) {
    float a = focal_elem(p.x, t.x);
    a += focal_elem(p.y, t.y);
    a += focal_elem(p.z, t.z);
    a += focal_elem(p.w, t.w);
    return a;
}

__global__ void __launch_bounds__(NTHREADS, 8)
focal_fused_kernel(const float4* __restrict__ p4,
                   const int4*   __restrict__ t4,
                   int nvec, int ntail,
                   const float* __restrict__ p_tail,
                   const int*   __restrict__ t_tail,
                   float* __restrict__ out, float inv_n) {
    const int stride = gridDim.x * blockDim.x;
    int i = blockIdx.x * blockDim.x + threadIdx.x;

    float acc = 0.0f;

    if (i < nvec) {
        // prime the pipeline
        float4 pc = p4[i];
        int4   tc = t4[i];
        int    in = i + stride;

        while (in < nvec) {
            // issue next loads before consuming current values
            float4 pn = p4[in];
            int4   tn = t4[in];
            acc += focal_vec(pc, tc);
            pc = pn;
            tc = tn;
            in += stride;
        }
        acc += focal_vec(pc, tc);
    }

    if (blockIdx.x == 0) {
        for (int k = threadIdx.x; k < ntail; k += blockDim.x)
            acc += focal_elem(p_tail[k], t_tail[k]);
    }

    // intra-block reduce
    #pragma unroll
    for (int off = 16; off > 0; off >>= 1)
        acc += __shfl_xor_sync(0xFFFFFFFFu, acc, off);

    __shared__ float smem[NTHREADS / 32];
    int lane = threadIdx.x & 31;
    int wid  = threadIdx.x >> 5;
    if (lane == 0) smem[wid] = acc;
    __syncthreads();

    __shared__ bool s_last;
    if (threadIdx.x == 0) {
        float v = 0.0f;
        #pragma unroll
        for (int w = 0; w < NTHREADS / 32; w++) v += smem[w];
        g_partials[blockIdx.x] = v;
        __threadfence();
        unsigned int prev = atomicAdd(&g_count, 1u);
        s_last = (prev == (unsigned int)(gridDim.x - 1));
    }
    __syncthreads();

    if (s_last) {
        // deterministic final reduction: fixed per-thread order, then tree
        float v = 0.0f;
        #pragma unroll
        for (int k = threadIdx.x; k < NBLOCKS; k += NTHREADS)
            v += g_partials[k];

        #pragma unroll
        for (int off = 16; off > 0; off >>= 1)
            v += __shfl_xor_sync(0xFFFFFFFFu, v, off);

        if (lane == 0) smem[wid] = v;
        __syncthreads();

        if (wid == 0) {
            float s = (lane < NTHREADS / 32) ? smem[lane] : 0.0f;
            #pragma unroll
            for (int off = 4; off > 0; off >>= 1)
                s += __shfl_xor_sync(0xFFFFFFFFu, s, off);
            if (lane == 0) {
                out[0] = s * inv_n;
                g_count = 0;           // reset for next graph replay
                __threadfence();
            }
        }
    }
}

extern "C" void kernel_launch(void* const* d_in, const int* in_sizes, int n_in,
                              void* d_out, int out_size) {
    const float* p = (const float*)d_in[0];
    const int*   t = (const int*)d_in[1];
    int n = in_sizes[0];

    int nvec  = n >> 2;
    int ntail = n - (nvec << 2);

    focal_fused_kernel<<<NBLOCKS, NTHREADS>>>(
        (const float4*)p, (const int4*)t, nvec, ntail,
        p + (nvec << 2), t + (nvec << 2),
        (float*)d_out, 1.0f / (float)n);
}